// round 11
// baseline (speedup 1.0000x reference)
#include <cuda_runtime.h>
#include <cuda_fp16.h>
#include <math.h>
#include <stdint.h>

#define B_  4
#define S_  1000
#define D_  512
#define H_  8
#define L_  4
#define V_  32000
#define HD_ 64
#define FF_ 2048
#define M_  (B_*S_)
#define SP_ 1024

// ======================= scratch (device globals, zero-init) =================
__device__ __align__(128) float g_x[M_*D_];
__device__ __align__(128) float g_t[M_*D_];
__device__ __align__(128) float g_qkvb[3*D_];
__device__ __align__(128) __half g_ah[M_*D_];                      // x fp16
__device__ __align__(128) __half g_hh[M_*FF_];                     // FFN mid fp16
__device__ __align__(128) __half g_qh[M_*D_];                      // Q, then ctx
__device__ __align__(128) __half g_kh[M_*D_];
__device__ __align__(128) __half g_bh[(size_t)V_*D_];              // W^T fp16
__device__ __align__(128) __half g_vh[(size_t)B_*H_*HD_*SP_];      // V^T (pad=0)

// ======================= helpers =============================================
__device__ __forceinline__ uint32_t smem_u32(const void* p){
    uint32_t a;
    asm("{ .reg .u64 t; cvta.to.shared.u64 t, %1; cvt.u32.u64 %0, t; }" : "=r"(a) : "l"(p));
    return a;
}
__device__ __forceinline__ uint32_t pack_h2(float a, float b){
    __half2 h = __floats2half2_rn(a, b);
    return *reinterpret_cast<uint32_t*>(&h);
}
__device__ __forceinline__ void ldm_x4(uint32_t* r, uint32_t addr){
    asm volatile("ldmatrix.sync.aligned.m8n8.x4.shared.b16 {%0,%1,%2,%3}, [%4];"
        : "=r"(r[0]), "=r"(r[1]), "=r"(r[2]), "=r"(r[3]) : "r"(addr));
}
#define MMAF16(c, a, b0v, b1v) \
    asm volatile("mma.sync.aligned.m16n8k16.row.col.f32.f16.f16.f32 " \
        "{%0,%1,%2,%3}, {%4,%5,%6,%7}, {%8,%9}, {%0,%1,%2,%3};" \
        : "+f"((c)[0]), "+f"((c)[1]), "+f"((c)[2]), "+f"((c)[3]) \
        : "r"((a)[0]), "r"((a)[1]), "r"((a)[2]), "r"((a)[3]), "r"(b0v), "r"(b1v))
#define CP_COMMIT() asm volatile("cp.async.commit_group;" ::: "memory")

// ======================= smem tile layout ====================================
#define SROW_B   80
#define MAT_B    (128*SROW_B)
#define NSTG     4
#define SMEM_TMM (NSTG*2*MAT_B)     // 81920 -> 2 CTA/SM

// 128 rows x 32 cols fp16 chunk, OOB rows clamped
__device__ __forceinline__ void cp_tile(const __half* __restrict__ g, int ld,
                                        int row0, int rowmax, int k0,
                                        uint32_t dst, int tid)
{
#pragma unroll
    for (int c = 0; c < 2; c++) {
        int idx = tid + c*256;
        int r = idx >> 2, q = idx & 3;
        int gr = row0 + r;
        int grc = gr < rowmax ? gr : (rowmax - 1);
        const char* src = (const char*)(g + (size_t)grc*ld + k0) + q*16;
        uint32_t d = dst + r*SROW_B + q*16;
        asm volatile("cp.async.cg.shared.global [%0], [%1], 16;"
            :: "r"(d), "l"(src));
    }
}
// 64 rows x 32 cols fp16 chunk (always in-bounds)
__device__ __forceinline__ void cp_tile64(const __half* __restrict__ g, int ld,
                                          int k0, uint32_t dst, int tid)
{
    int r = tid >> 2, q = tid & 3;
    const char* src = (const char*)(g + (size_t)r*ld + k0) + q*16;
    uint32_t d = dst + r*SROW_B + q*16;
    asm volatile("cp.async.cg.shared.global [%0], [%1], 16;"
        :: "r"(d), "l"(src));
}

// ======================= fp16 mma.sync GEMM (single pass) ====================
// C = act(alpha * Ah @ Bh^T + bias)
// outmode 0: fp32 C | 2: fp16 -> Oh
// outmode 4: merged QKV: c0<512 -> Oh(q), <1024 -> Ol(k), else V^T -> (half*)C
__global__ __launch_bounds__(256, 2)
void tmm_kernel(const __half* __restrict__ Ah, int lda,
                const __half* __restrict__ Bh, int ldb,
                const float* __restrict__ bias,
                float* __restrict__ C,
                __half* __restrict__ Oh, __half* __restrict__ Ol, int ldc,
                int Mv, int Nv, int K,
                float alpha, int relu, int outmode)
{
    extern __shared__ char sm[];
    const uint32_t sb = smem_u32(sm);
    const int tid  = threadIdx.x;
    const int wid  = tid >> 5;
    const int lane = tid & 31;

    const int m0 = blockIdx.y * 128;
    const int n0 = blockIdx.x * 128;
    const int wm = (wid >> 2) * 64;
    const int wn = (wid & 3) * 32;
    const int rem = Nv - n0 - wn;

    const uint32_t aoff = (uint32_t)(wm + (lane & 15)) * SROW_B + ((lane >> 4) * 16);
    const uint32_t boff = (uint32_t)(wn + (lane & 7) + ((lane >> 4) * 8)) * SROW_B
                        + (((lane >> 3) & 1) * 16);

    float acc[4][4][4];
#pragma unroll
    for (int i = 0; i < 4; i++)
#pragma unroll
        for (int j = 0; j < 4; j++)
#pragma unroll
            for (int e = 0; e < 4; e++) acc[i][j][e] = 0.f;

    const int NC = K >> 5;

    auto issue = [&](int s){
        uint32_t base = sb + (s % NSTG) * (2*MAT_B);
        int k0 = s << 5;
        cp_tile(Ah, lda, m0, Mv, k0, base + 0*MAT_B, tid);
        cp_tile(Bh, ldb, n0, Nv, k0, base + 1*MAT_B, tid);
    };

#pragma unroll
    for (int s = 0; s < NSTG-1; s++) {
        if (s < NC) issue(s);
        CP_COMMIT();
    }

    for (int kc = 0; kc < NC; kc++) {
        asm volatile("cp.async.wait_group 2;" ::: "memory");
        __syncthreads();
        const uint32_t base = sb + (kc % NSTG) * (2*MAT_B);
        const uint32_t aBH = base + 0*MAT_B + aoff;
        const uint32_t bBH = base + 1*MAT_B + boff;

#pragma unroll
        for (int ks = 0; ks < 2; ks++) {
            uint32_t ah[4][4], bh[2][4];
#pragma unroll
            for (int mt = 0; mt < 4; mt++) ldm_x4(ah[mt], aBH + mt*(16*SROW_B) + ks*32);
#pragma unroll
            for (int p = 0; p < 2; p++)
                if (p*16 < rem) ldm_x4(bh[p], bBH + p*(16*SROW_B) + ks*32);
#pragma unroll
            for (int mt = 0; mt < 4; mt++)
#pragma unroll
                for (int nt = 0; nt < 4; nt++)
                    if (nt*8 < rem) {
                        uint32_t b0 = bh[nt>>1][(nt&1)*2], b1 = bh[nt>>1][(nt&1)*2+1];
                        MMAF16(acc[mt][nt], ah[mt], b0, b1);
                    }
        }
        if (kc + NSTG - 1 < NC) issue(kc + NSTG - 1);
        CP_COMMIT();
    }

    const int gq = lane >> 2;
    const int tg = lane & 3;
#pragma unroll
    for (int mt = 0; mt < 4; mt++) {
#pragma unroll
        for (int half_ = 0; half_ < 2; half_++) {
            int r = m0 + wm + mt*16 + gq + half_*8;
            if (r >= Mv) continue;
#pragma unroll
            for (int nt = 0; nt < 4; nt++) {
                int c0 = n0 + wn + nt*8 + tg*2;
                if (c0 >= Nv) continue;
                float v0 = alpha*acc[mt][nt][half_*2+0];
                float v1 = alpha*acc[mt][nt][half_*2+1];
                if (bias) { v0 += bias[c0]; v1 += bias[c0+1]; }
                if (relu) { v0 = fmaxf(v0, 0.f); v1 = fmaxf(v1, 0.f); }
                if (outmode == 0) {
                    *reinterpret_cast<float2*>(C + (size_t)r*ldc + c0) = make_float2(v0, v1);
                } else if (outmode == 2) {
                    *reinterpret_cast<__half2*>(Oh + (size_t)r*ldc + c0) =
                        __half2(__float2half(v0), __float2half(v1));
                } else {
                    if (c0 < 1024) {
                        __half2 hv(__float2half(v0), __float2half(v1));
                        if (c0 < 512)
                            *reinterpret_cast<__half2*>(Oh + (size_t)r*D_ + c0) = hv;
                        else
                            *reinterpret_cast<__half2*>(Ol + (size_t)r*D_ + (c0-512)) = hv;
                    } else {
                        __half* Vt = reinterpret_cast<__half*>(C);
                        int b = r / S_, s = r - b*S_;
                        int cc = c0 - 1024;
                        int hi = cc >> 6, di = cc & 63;
                        Vt[(((size_t)b*H_ + hi)*HD_ + di    )*SP_ + s] = __float2half(v0);
                        Vt[(((size_t)b*H_ + hi)*HD_ + di + 1)*SP_ + s] = __float2half(v1);
                    }
                }
            }
        }
    }
}

// ======================= fused flash attention ===============================
// grid (S/128, B*H), 256 thr. Each warp owns 16 q-rows x full 128-col k-tile.
// O (ctx, fp16) written in place over Q buffer (disjoint per-CTA regions).
#define FQ_OFF     0
#define FK_OFF(s)  (20480 + (s)*20480)
#define FV_OFF(s)  (61440 + (s)*20480)
#define FLASH_SMEM 102400

__global__ __launch_bounds__(256, 1)
void flash_kernel(const __half* __restrict__ Q, const __half* __restrict__ Kp,
                  const __half* __restrict__ Vt, __half* __restrict__ O)
{
    extern __shared__ char sm[];
    const uint32_t sb = smem_u32(sm);
    const int tid = threadIdx.x, wid = tid >> 5, lane = tid & 31;
    const int z = blockIdx.y, zb = z / H_, zh = z % H_;
    const int q0 = blockIdx.x * 128;
    const int wr = wid * 16;
    const int gq = lane >> 2, tg = lane & 3;

    const __half* Qg = Q  + (size_t)zb*S_*D_ + zh*HD_;
    const __half* Kg = Kp + (size_t)zb*S_*D_ + zh*HD_;
    const __half* Vg = Vt + (size_t)z*HD_*SP_;

    auto issueKV = [&](int kt){
        uint32_t ks = sb + FK_OFF(kt & 1), vs = sb + FV_OFF(kt & 1);
        cp_tile(Kg, D_, kt*128, S_, 0,  ks,         tid);
        cp_tile(Kg, D_, kt*128, S_, 32, ks + 10240, tid);
        cp_tile64(Vg, SP_, kt*128 +  0, vs +     0, tid);
        cp_tile64(Vg, SP_, kt*128 + 32, vs +  5120, tid);
        cp_tile64(Vg, SP_, kt*128 + 64, vs + 10240, tid);
        cp_tile64(Vg, SP_, kt*128 + 96, vs + 15360, tid);
    };

    cp_tile(Qg, D_, q0, S_, 0,  sb + FQ_OFF,         tid);
    cp_tile(Qg, D_, q0, S_, 32, sb + FQ_OFF + 10240, tid);
    issueKV(0);
    CP_COMMIT();

    float m0 = -1e30f, m1 = -1e30f, l0 = 0.f, l1 = 0.f;
    float oacc[8][4];
#pragma unroll
    for (int i = 0; i < 8; i++)
#pragma unroll
        for (int e = 0; e < 4; e++) oacc[i][e] = 0.f;
    uint32_t qf[4][4];

    const uint32_t aoff = (uint32_t)(wr + (lane & 15)) * SROW_B + ((lane >> 4) * 16);
    const uint32_t bo   = (uint32_t)((lane & 7) + ((lane >> 4) * 8)) * SROW_B
                        + (((lane >> 3) & 1) * 16);

    for (int kt = 0; kt < 8; kt++) {
        if (kt < 7) issueKV(kt + 1);
        CP_COMMIT();
        asm volatile("cp.async.wait_group 1;" ::: "memory");
        __syncthreads();

        if (kt == 0) {
#pragma unroll
            for (int ks = 0; ks < 4; ks++)
                ldm_x4(qf[ks], sb + FQ_OFF + (ks >> 1)*10240 + aoff + (ks & 1)*32);
        }

        // ---- S = Q @ K^T ----
        float sacc[16][4];
#pragma unroll
        for (int i = 0; i < 16; i++)
#pragma unroll
            for (int e = 0; e < 4; e++) sacc[i][e] = 0.f;
        const uint32_t skb = sb + FK_OFF(kt & 1);
#pragma unroll
        for (int g16 = 0; g16 < 8; g16++) {
#pragma unroll
            for (int ks = 0; ks < 4; ks++) {
                uint32_t kb[4];
                ldm_x4(kb, skb + (ks >> 1)*10240 + g16*(16*SROW_B) + bo + (ks & 1)*32);
                MMAF16(sacc[2*g16],   qf[ks], kb[0], kb[1]);
                MMAF16(sacc[2*g16+1], qf[ks], kb[2], kb[3]);
            }
        }

        // ---- scale + mask ----
        const int kcb = kt*128 + tg*2;
        if (kt == 7) {
#pragma unroll
            for (int nt = 0; nt < 16; nt++) {
                int kc = kcb + nt*8;
                float s0 = (kc   < S_) ? sacc[nt][0]*0.125f : -1e30f;
                float s1 = (kc+1 < S_) ? sacc[nt][1]*0.125f : -1e30f;
                float s2 = (kc   < S_) ? sacc[nt][2]*0.125f : -1e30f;
                float s3 = (kc+1 < S_) ? sacc[nt][3]*0.125f : -1e30f;
                sacc[nt][0]=s0; sacc[nt][1]=s1; sacc[nt][2]=s2; sacc[nt][3]=s3;
            }
        } else {
#pragma unroll
            for (int nt = 0; nt < 16; nt++)
#pragma unroll
                for (int e = 0; e < 4; e++) sacc[nt][e] *= 0.125f;
        }

        // ---- online softmax ----
        float rm0 = -1e30f, rm1 = -1e30f;
#pragma unroll
        for (int nt = 0; nt < 16; nt++) {
            rm0 = fmaxf(rm0, fmaxf(sacc[nt][0], sacc[nt][1]));
            rm1 = fmaxf(rm1, fmaxf(sacc[nt][2], sacc[nt][3]));
        }
        rm0 = fmaxf(rm0, __shfl_xor_sync(0xffffffffu, rm0, 1));
        rm0 = fmaxf(rm0, __shfl_xor_sync(0xffffffffu, rm0, 2));
        rm1 = fmaxf(rm1, __shfl_xor_sync(0xffffffffu, rm1, 1));
        rm1 = fmaxf(rm1, __shfl_xor_sync(0xffffffffu, rm1, 2));
        float mn0 = fmaxf(m0, rm0), mn1 = fmaxf(m1, rm1);
        float c0 = __expf(m0 - mn0), c1 = __expf(m1 - mn1);
        m0 = mn0; m1 = mn1;

        float rs0 = 0.f, rs1 = 0.f;
#pragma unroll
        for (int nt = 0; nt < 16; nt++) {
            float p0 = __expf(sacc[nt][0] - m0);
            float p1 = __expf(sacc[nt][1] - m0);
            float p2 = __expf(sacc[nt][2] - m1);
            float p3 = __expf(sacc[nt][3] - m1);
            sacc[nt][0]=p0; sacc[nt][1]=p1; sacc[nt][2]=p2; sacc[nt][3]=p3;
            rs0 += p0 + p1;  rs1 += p2 + p3;
        }
        rs0 += __shfl_xor_sync(0xffffffffu, rs0, 1);
        rs0 += __shfl_xor_sync(0xffffffffu, rs0, 2);
        rs1 += __shfl_xor_sync(0xffffffffu, rs1, 1);
        rs1 += __shfl_xor_sync(0xffffffffu, rs1, 2);
        l0 = l0*c0 + rs0;  l1 = l1*c1 + rs1;
#pragma unroll
        for (int no = 0; no < 8; no++) {
            oacc[no][0] *= c0; oacc[no][1] *= c0;
            oacc[no][2] *= c1; oacc[no][3] *= c1;
        }

        // ---- O += P @ V ----
        const uint32_t svb = sb + FV_OFF(kt & 1);
#pragma unroll
        for (int j = 0; j < 8; j++) {
            uint32_t af[4];
            af[0] = pack_h2(sacc[2*j][0],   sacc[2*j][1]);
            af[1] = pack_h2(sacc[2*j][2],   sacc[2*j][3]);
            af[2] = pack_h2(sacc[2*j+1][0], sacc[2*j+1][1]);
            af[3] = pack_h2(sacc[2*j+1][2], sacc[2*j+1][3]);
#pragma unroll
            for (int gn = 0; gn < 4; gn++) {
                uint32_t vb[4];
                ldm_x4(vb, svb + (j >> 1)*5120 + gn*(16*SROW_B) + bo + (j & 1)*32);
                MMAF16(oacc[2*gn],   af, vb[0], vb[1]);
                MMAF16(oacc[2*gn+1], af, vb[2], vb[3]);
            }
        }
        __syncthreads();
    }

    // ---- epilogue: O /= l, store fp16 ----
    float inv0 = 1.f / l0, inv1 = 1.f / l1;
    int r0 = q0 + wr + gq, r1 = r0 + 8;
    __half* Orow0 = O + ((size_t)zb*S_ + r0)*D_ + zh*HD_;
    __half* Orow1 = O + ((size_t)zb*S_ + r1)*D_ + zh*HD_;
#pragma unroll
    for (int no = 0; no < 8; no++) {
        int col = no*8 + tg*2;
        if (r0 < S_)
            *reinterpret_cast<__half2*>(Orow0 + col) =
                __floats2half2_rn(oacc[no][0]*inv0, oacc[no][1]*inv0);
        if (r1 < S_)
            *reinterpret_cast<__half2*>(Orow1 + col) =
                __floats2half2_rn(oacc[no][2]*inv1, oacc[no][3]*inv1);
    }
}

// ======================= weight transpose -> fp16 ============================
__global__ void wsplit_t(const float* __restrict__ W,
                         __half* __restrict__ oh, int K, int N)
{
    __shared__ float t[32][33];
    int n = blockIdx.x*32 + threadIdx.x;
    int k0 = blockIdx.y*32;
    #pragma unroll
    for (int j = 0; j < 4; j++)
        t[threadIdx.y + j*8][threadIdx.x] = W[(size_t)(k0 + threadIdx.y + j*8)*N + n];
    __syncthreads();
    int k = k0 + threadIdx.x;
    #pragma unroll
    for (int j = 0; j < 4; j++) {
        int nn = blockIdx.x*32 + threadIdx.y + j*8;
        oh[(size_t)nn*K + k] = __float2half(t[threadIdx.x][threadIdx.y + j*8]);
    }
}

// ======================= merged QKV bias =====================================
__global__ void qkv_bias(const float* __restrict__ bq, const float* __restrict__ bk,
                         const float* __restrict__ bv, float* __restrict__ o)
{
    int i = blockIdx.x*256 + threadIdx.x;
    o[i] = (i < 512) ? bq[i] : (i < 1024 ? bk[i-512] : bv[i-1024]);
}

// ======================= embed + posenc ======================================
__global__ void embed_kernel(const int* __restrict__ tokens,
                             const float* __restrict__ emb,
                             float* __restrict__ x,
                             __half* __restrict__ oh)
{
    int row = blockIdx.x, d = threadIdx.x;
    int s = row % S_;
    int tok = tokens[row];
    int i = d >> 1;
    float dv  = expf(-(float)(2*i) * (9.210340371976184f / (float)D_));
    float arg = (float)s * dv;
    float pe  = (d & 1) ? cosf(arg) : sinf(arg);
    float val = emb[(size_t)tok*D_ + d] + pe;
    size_t idx = (size_t)row*D_ + d;
    x[idx] = val;
    oh[idx] = __float2half(val);
}

// ======================= final V-softmax (smem row, 512 thr) =================
__global__ void softmax_big(float* __restrict__ data)
{
    extern __shared__ float row[];
    float* p = data + (size_t)blockIdx.x * V_;
    const int tid = threadIdx.x, lane = tid & 31, wrp = tid >> 5;
    __shared__ float bm[16], bs[16];
    __shared__ float s_m, s_inv;

    float m = -3.4e38f;
    for (int i = tid; i < V_; i += 512) { float v = p[i]; row[i] = v; m = fmaxf(m, v); }
    #pragma unroll
    for (int o = 16; o; o >>= 1) m = fmaxf(m, __shfl_xor_sync(0xffffffffu, m, o));
    if (lane == 0) bm[wrp] = m;
    __syncthreads();
    if (tid == 0) {
        float t = bm[0];
        #pragma unroll
        for (int i = 1; i < 16; i++) t = fmaxf(t, bm[i]);
        s_m = t;
    }
    __syncthreads();
    m = s_m;
    float s = 0.f;
    for (int i = tid; i < V_; i += 512) s += __expf(row[i] - m);
    #pragma unroll
    for (int o = 16; o; o >>= 1) s += __shfl_xor_sync(0xffffffffu, s, o);
    if (lane == 0) bs[wrp] = s;
    __syncthreads();
    if (tid == 0) {
        float t = 0.f;
        #pragma unroll
        for (int i = 0; i < 16; i++) t += bs[i];
        s_inv = 1.0f / t;
    }
    __syncthreads();
    const float mm = s_m, inv = s_inv;
    for (int i = tid; i < V_; i += 512)
        p[i] = __expf(row[i] - mm) * inv;
}

// ======================= residual add + LayerNorm ============================
__global__ void add_ln_kernel(const float* __restrict__ xin,
                              const float* __restrict__ res,
                              const float* __restrict__ g,
                              const float* __restrict__ b,
                              float* __restrict__ xout,
                              __half* __restrict__ oh)
{
    const int row = blockIdx.x, d = threadIdx.x;
    const int lane = d & 31, wrp = d >> 5;
    size_t idx = (size_t)row*D_ + d;
    float y = xin[idx] + res[idx];
    __shared__ float bsum[16], bsq[16];
    __shared__ float s_mu, s_rs;
    float s1 = y, s2 = y*y;
    #pragma unroll
    for (int o = 16; o; o >>= 1) {
        s1 += __shfl_xor_sync(0xffffffffu, s1, o);
        s2 += __shfl_xor_sync(0xffffffffu, s2, o);
    }
    if (lane == 0) { bsum[wrp] = s1; bsq[wrp] = s2; }
    __syncthreads();
    if (d == 0) {
        float a = 0.f, c = 0.f;
        #pragma unroll
        for (int i = 0; i < 16; i++) { a += bsum[i]; c += bsq[i]; }
        float mu = a * (1.0f/D_);
        float var = c * (1.0f/D_) - mu*mu;
        s_mu = mu; s_rs = rsqrtf(var + 1e-5f);
    }
    __syncthreads();
    float val = (y - s_mu) * s_rs * g[d] + b[d];
    xout[idx] = val;
    oh[idx] = __float2half(val);
}

// ======================= launcher ============================================
extern "C" void kernel_launch(void* const* d_in, const int* in_sizes, int n_in,
                              void* d_out, int out_size)
{
    (void)in_sizes; (void)n_in; (void)out_size;
    const int*   tokens = (const int*)  d_in[0];
    const float* emb  = (const float*)d_in[1];
    const float* wq   = (const float*)d_in[2];
    const float* bq   = (const float*)d_in[3];
    const float* wk   = (const float*)d_in[4];
    const float* bk   = (const float*)d_in[5];
    const float* wv   = (const float*)d_in[6];
    const float* bv   = (const float*)d_in[7];
    const float* wo   = (const float*)d_in[8];
    const float* bo   = (const float*)d_in[9];
    const float* ln1g = (const float*)d_in[10];
    const float* ln1b = (const float*)d_in[11];
    const float* w1   = (const float*)d_in[12];
    const float* b1   = (const float*)d_in[13];
    const float* w2   = (const float*)d_in[14];
    const float* b2   = (const float*)d_in[15];
    const float* ln2g = (const float*)d_in[16];
    const float* ln2b = (const float*)d_in[17];
    const float* fcw  = (const float*)d_in[18];
    const float* fcb  = (const float*)d_in[19];
    float* out = (float*)d_out;

    float *x,*t,*qkvb;
    __half *ah,*hh,*qh,*kh,*bh,*vh;
    cudaGetSymbolAddress((void**)&x,  g_x);  cudaGetSymbolAddress((void**)&t,  g_t);
    cudaGetSymbolAddress((void**)&qkvb, g_qkvb);
    cudaGetSymbolAddress((void**)&ah, g_ah); cudaGetSymbolAddress((void**)&hh, g_hh);
    cudaGetSymbolAddress((void**)&qh, g_qh); cudaGetSymbolAddress((void**)&kh, g_kh);
    cudaGetSymbolAddress((void**)&bh, g_bh); cudaGetSymbolAddress((void**)&vh, g_vh);

    cudaFuncSetAttribute(tmm_kernel,  cudaFuncAttributeMaxDynamicSharedMemorySize, SMEM_TMM);
    cudaFuncSetAttribute(flash_kernel, cudaFuncAttributeMaxDynamicSharedMemorySize, FLASH_SMEM);
    cudaFuncSetAttribute(softmax_big, cudaFuncAttributeMaxDynamicSharedMemorySize, V_*4);

    embed_kernel<<<M_, D_>>>(tokens, emb, x, ah);

    const dim3 gQKV(1536/128, (M_+127)/128);
    const dim3 gDD (D_/128,  (M_+127)/128);
    const dim3 gFF (FF_/128, (M_+127)/128);
    const dim3 gFL (8, B_*H_);
    const dim3 tb (32, 8);

    for (int l = 0; l < L_; l++) {
        const float* lwq = wq + (size_t)l*D_*D_;
        const float* lwk = wk + (size_t)l*D_*D_;
        const float* lwv = wv + (size_t)l*D_*D_;
        const float* lwo = wo + (size_t)l*D_*D_;
        const float* lw1 = w1 + (size_t)l*D_*FF_;
        const float* lw2 = w2 + (size_t)l*FF_*D_;

        // ---- merged QKV projection ----
        qkv_bias<<<6, 256>>>(bq + l*D_, bk + l*D_, bv + l*D_, qkvb);
        wsplit_t<<<dim3(D_/32, D_/32), tb>>>(lwq, bh,           D_, D_);
        wsplit_t<<<dim3(D_/32, D_/32), tb>>>(lwk, bh +  512*D_, D_, D_);
        wsplit_t<<<dim3(D_/32, D_/32), tb>>>(lwv, bh + 1024*D_, D_, D_);
        tmm_kernel<<<gQKV, 256, SMEM_TMM>>>(ah, D_, bh, D_,
            qkvb, (float*)vh, qh, kh, D_, M_, 1536, D_, 1.f, 0, 4);

        // ---- fused attention: ctx written over qh ----
        flash_kernel<<<gFL, 256, FLASH_SMEM>>>(qh, kh, vh, qh);

        // ---- output projection ----
        wsplit_t<<<dim3(D_/32, D_/32), tb>>>(lwo, bh, D_, D_);
        tmm_kernel<<<gDD, 256, SMEM_TMM>>>(qh, D_, bh, D_,
            bo + l*D_, t, nullptr, nullptr, D_, M_, D_, D_, 1.f, 0, 0);

        add_ln_kernel<<<M_, D_>>>(x, t, ln1g + l*D_, ln1b + l*D_, x, ah);

        // ---- FFN ----
        wsplit_t<<<dim3(FF_/32, D_/32), tb>>>(lw1, bh, D_, FF_);
        tmm_kernel<<<gFF, 256, SMEM_TMM>>>(ah, D_, bh, D_,
            b1 + l*FF_, nullptr, hh, nullptr, FF_, M_, FF_, D_, 1.f, 1, 2);
        wsplit_t<<<dim3(D_/32, FF_/32), tb>>>(lw2, bh, FF_, D_);
        tmm_kernel<<<gDD, 256, SMEM_TMM>>>(hh, FF_, bh, FF_,
            b2 + l*D_, t, nullptr, nullptr, D_, M_, D_, FF_, 1.f, 0, 0);

        add_ln_kernel<<<M_, D_>>>(x, t, ln2g + l*D_, ln2b + l*D_, x, ah);
    }

    // ---- logits + softmax ----
    wsplit_t<<<dim3(V_/32, D_/32), tb>>>(fcw, bh, D_, V_);
    tmm_kernel<<<dim3(V_/128, (M_+127)/128), 256, SMEM_TMM>>>(ah, D_, bh, D_,
        fcb, out, nullptr, nullptr, V_, M_, V_, D_, 1.f, 0, 0);
    softmax_big<<<M_, 512, V_*4>>>(out);
}

// round 12
// speedup vs baseline: 1.1858x; 1.1858x over previous
#include <cuda_runtime.h>
#include <cuda_fp16.h>
#include <math.h>
#include <stdint.h>

#define B_  4
#define S_  1000
#define D_  512
#define H_  8
#define L_  4
#define V_  32000
#define HD_ 64
#define FF_ 2048
#define M_  (B_*S_)
#define SP_ 1024

// ======================= scratch (device globals, zero-init) =================
__device__ __align__(128) float g_x[M_*D_];
__device__ __align__(128) float g_t[M_*D_];
__device__ __align__(128) __half g_sc[(size_t)B_*H_*S_*S_];        // scores fp16
__device__ __align__(128) float g_qkvb[3*D_];
__device__ __align__(128) __half g_ah[M_*D_];                      // x fp16
__device__ __align__(128) __half g_hh[M_*FF_];                     // FFN mid fp16
__device__ __align__(128) __half g_qh[M_*D_];
__device__ __align__(128) __half g_kh[M_*D_];
__device__ __align__(128) __half g_bh[(size_t)V_*D_];              // W^T fp16
__device__ __align__(128) __half g_sh[(size_t)B_*H_*S_*SP_];       // probs (pad=0)
__device__ __align__(128) __half g_vh[(size_t)B_*H_*HD_*SP_];      // V^T (pad=0)

// ======================= helpers =============================================
__device__ __forceinline__ uint32_t smem_u32(const void* p){
    uint32_t a;
    asm("{ .reg .u64 t; cvta.to.shared.u64 t, %1; cvt.u32.u64 %0, t; }" : "=r"(a) : "l"(p));
    return a;
}
__device__ __forceinline__ void ldm_x4(uint32_t* r, uint32_t addr){
    asm volatile("ldmatrix.sync.aligned.m8n8.x4.shared.b16 {%0,%1,%2,%3}, [%4];"
        : "=r"(r[0]), "=r"(r[1]), "=r"(r[2]), "=r"(r[3]) : "r"(addr));
}
#define MMAF16(c, a, b0v, b1v) \
    asm volatile("mma.sync.aligned.m16n8k16.row.col.f32.f16.f16.f32 " \
        "{%0,%1,%2,%3}, {%4,%5,%6,%7}, {%8,%9}, {%0,%1,%2,%3};" \
        : "+f"((c)[0]), "+f"((c)[1]), "+f"((c)[2]), "+f"((c)[3]) \
        : "r"((a)[0]), "r"((a)[1]), "r"((a)[2]), "r"((a)[3]), "r"(b0v), "r"(b1v))
#define CP_COMMIT() asm volatile("cp.async.commit_group;" ::: "memory")

// ======================= smem tile layout (BK = 64) ==========================
#define SROW_B   144                 // 128B data + 16B pad (conflict-free)
#define MAT_B    (128*SROW_B)        // 18432 B per 128x64 fp16 tile
#define NSTG     3
#define SMEM_TMM (NSTG*2*MAT_B)      // 110592 -> 2 CTA/SM (221 KB)

// 128 rows x 64 cols fp16 chunk, OOB rows clamped
__device__ __forceinline__ void cp_tile(const __half* __restrict__ g, int ld,
                                        int row0, int rowmax, int k0,
                                        uint32_t dst, int tid)
{
#pragma unroll
    for (int c = 0; c < 4; c++) {
        int idx = tid + c*256;          // 0..1023
        int r = idx >> 3, q = idx & 7;  // row, 16B segment
        int gr = row0 + r;
        int grc = gr < rowmax ? gr : (rowmax - 1);
        const char* src = (const char*)(g + (size_t)grc*ld + k0) + q*16;
        uint32_t d = dst + r*SROW_B + q*16;
        asm volatile("cp.async.cg.shared.global [%0], [%1], 16;"
            :: "r"(d), "l"(src));
    }
}

// ======================= fp16 mma.sync GEMM (BK=64, batched) =================
// C = act(alpha * Ah @ Bh^T + bias)
// outmode 0: fp32 C | 2: fp16 -> Oh
// outmode 4: merged QKV: c0<512 -> Oh(q), <1024 -> Ol(k), else V^T -> (half*)C
__global__ __launch_bounds__(256, 2)
void tmm_kernel(const __half* __restrict__ Ah, int lda,
                const __half* __restrict__ Bh, int ldb,
                const float* __restrict__ bias,
                float* __restrict__ C,
                __half* __restrict__ Oh, __half* __restrict__ Ol, int ldc,
                int Mv, int Nv, int K,
                long long sAb, long long sAh, long long sBb, long long sBh,
                long long sCb, long long sCh,
                float alpha, int relu, int outmode)
{
    extern __shared__ char sm[];
    const uint32_t sb = smem_u32(sm);
    const int tid  = threadIdx.x;
    const int wid  = tid >> 5;
    const int lane = tid & 31;

    const long long zb = blockIdx.z / H_;
    const long long zh = blockIdx.z % H_;
    Ah += zb*sAb + zh*sAh;  Bh += zb*sBb + zh*sBh;
    const size_t cOff = (size_t)(zb*sCb + zh*sCh);

    const int m0 = blockIdx.y * 128;
    const int n0 = blockIdx.x * 128;
    const int wm = (wid >> 2) * 64;
    const int wn = (wid & 3) * 32;
    const int rem = Nv - n0 - wn;

    const uint32_t aoff = (uint32_t)(wm + (lane & 15)) * SROW_B + ((lane >> 4) * 16);
    const uint32_t boff = (uint32_t)(wn + (lane & 7) + ((lane >> 4) * 8)) * SROW_B
                        + (((lane >> 3) & 1) * 16);

    float acc[4][4][4];
#pragma unroll
    for (int i = 0; i < 4; i++)
#pragma unroll
        for (int j = 0; j < 4; j++)
#pragma unroll
            for (int e = 0; e < 4; e++) acc[i][j][e] = 0.f;

    const int NC = K >> 6;                      // BK = 64

    auto issue = [&](int s){
        uint32_t base = sb + (s % NSTG) * (2*MAT_B);
        int k0 = s << 6;
        cp_tile(Ah, lda, m0, Mv, k0, base + 0*MAT_B, tid);
        cp_tile(Bh, ldb, n0, Nv, k0, base + 1*MAT_B, tid);
    };

#pragma unroll
    for (int s = 0; s < NSTG-1; s++) {
        if (s < NC) issue(s);
        CP_COMMIT();
    }

    for (int kc = 0; kc < NC; kc++) {
        asm volatile("cp.async.wait_group 1;" ::: "memory");
        __syncthreads();
        const uint32_t base = sb + (kc % NSTG) * (2*MAT_B);
        const uint32_t aBH = base + 0*MAT_B + aoff;
        const uint32_t bBH = base + 1*MAT_B + boff;

#pragma unroll
        for (int ks = 0; ks < 4; ks++) {
            uint32_t ah[4][4], bh[2][4];
#pragma unroll
            for (int mt = 0; mt < 4; mt++) ldm_x4(ah[mt], aBH + mt*(16*SROW_B) + ks*32);
#pragma unroll
            for (int p = 0; p < 2; p++)
                if (p*16 < rem) ldm_x4(bh[p], bBH + p*(16*SROW_B) + ks*32);
#pragma unroll
            for (int mt = 0; mt < 4; mt++)
#pragma unroll
                for (int nt = 0; nt < 4; nt++)
                    if (nt*8 < rem) {
                        uint32_t b0 = bh[nt>>1][(nt&1)*2], b1 = bh[nt>>1][(nt&1)*2+1];
                        MMAF16(acc[mt][nt], ah[mt], b0, b1);
                    }
        }
        if (kc + NSTG - 1 < NC) issue(kc + NSTG - 1);
        CP_COMMIT();
    }

    // ---- epilogue ----
    const int gq = lane >> 2;
    const int tg = lane & 3;
#pragma unroll
    for (int mt = 0; mt < 4; mt++) {
#pragma unroll
        for (int half_ = 0; half_ < 2; half_++) {
            int r = m0 + wm + mt*16 + gq + half_*8;
            if (r >= Mv) continue;
#pragma unroll
            for (int nt = 0; nt < 4; nt++) {
                int c0 = n0 + wn + nt*8 + tg*2;
                if (c0 >= Nv) continue;
                float v0 = alpha*acc[mt][nt][half_*2+0];
                float v1 = alpha*acc[mt][nt][half_*2+1];
                if (bias) { v0 += bias[c0]; v1 += bias[c0+1]; }
                if (relu) { v0 = fmaxf(v0, 0.f); v1 = fmaxf(v1, 0.f); }
                if (outmode == 0) {
                    *reinterpret_cast<float2*>(C + cOff + (size_t)r*ldc + c0) = make_float2(v0, v1);
                } else if (outmode == 2) {
                    *reinterpret_cast<__half2*>(Oh + cOff + (size_t)r*ldc + c0) =
                        __half2(__float2half(v0), __float2half(v1));
                } else {
                    if (c0 < 1024) {
                        __half2 hv(__float2half(v0), __float2half(v1));
                        if (c0 < 512)
                            *reinterpret_cast<__half2*>(Oh + (size_t)r*D_ + c0) = hv;
                        else
                            *reinterpret_cast<__half2*>(Ol + (size_t)r*D_ + (c0-512)) = hv;
                    } else {
                        __half* Vt = reinterpret_cast<__half*>(C);
                        int b = r / S_, s = r - b*S_;
                        int cc = c0 - 1024;
                        int hi = cc >> 6, di = cc & 63;
                        Vt[(((size_t)b*H_ + hi)*HD_ + di    )*SP_ + s] = __float2half(v0);
                        Vt[(((size_t)b*H_ + hi)*HD_ + di + 1)*SP_ + s] = __float2half(v1);
                    }
                }
            }
        }
    }
}

// ======================= weight transpose -> fp16 ============================
__global__ void wsplit_t(const float* __restrict__ W,
                         __half* __restrict__ oh, int K, int N)
{
    __shared__ float t[32][33];
    int n = blockIdx.x*32 + threadIdx.x;
    int k0 = blockIdx.y*32;
    #pragma unroll
    for (int j = 0; j < 4; j++)
        t[threadIdx.y + j*8][threadIdx.x] = W[(size_t)(k0 + threadIdx.y + j*8)*N + n];
    __syncthreads();
    int k = k0 + threadIdx.x;
    #pragma unroll
    for (int j = 0; j < 4; j++) {
        int nn = blockIdx.x*32 + threadIdx.y + j*8;
        oh[(size_t)nn*K + k] = __float2half(t[threadIdx.x][threadIdx.y + j*8]);
    }
}

// ======================= merged QKV bias =====================================
__global__ void qkv_bias(const float* __restrict__ bq, const float* __restrict__ bk,
                         const float* __restrict__ bv, float* __restrict__ o)
{
    int i = blockIdx.x*256 + threadIdx.x;
    o[i] = (i < 512) ? bq[i] : (i < 1024 ? bk[i-512] : bv[i-1024]);
}

// ======================= embed + posenc ======================================
__global__ void embed_kernel(const int* __restrict__ tokens,
                             const float* __restrict__ emb,
                             float* __restrict__ x,
                             __half* __restrict__ oh)
{
    int row = blockIdx.x, d = threadIdx.x;
    int s = row % S_;
    int tok = tokens[row];
    int i = d >> 1;
    float dv  = expf(-(float)(2*i) * (9.210340371976184f / (float)D_));
    float arg = (float)s * dv;
    float pe  = (d & 1) ? cosf(arg) : sinf(arg);
    float val = emb[(size_t)tok*D_ + d] + pe;
    size_t idx = (size_t)row*D_ + d;
    x[idx] = val;
    oh[idx] = __float2half(val);
}

// ======================= scores softmax (fp16 in) -> fp16 probs ==============
__global__ void softmax_split(const __half* __restrict__ sc,
                              __half* __restrict__ oh)
{
    __shared__ float row[S_];
    __shared__ float bm[8], bs[8];
    __shared__ float s_m, s_inv;
    int z = blockIdx.x / S_, r = blockIdx.x % S_;
    const __half* p = sc + (size_t)z*S_*S_ + (size_t)r*S_;
    const int tid = threadIdx.x, lane = tid & 31, wrp = tid >> 5;

    float m = -3.4e38f;
    for (int i = tid; i < S_; i += 256) { float v = __half2float(p[i]); row[i] = v; m = fmaxf(m, v); }
    #pragma unroll
    for (int o = 16; o; o >>= 1) m = fmaxf(m, __shfl_xor_sync(0xffffffffu, m, o));
    if (lane == 0) bm[wrp] = m;
    __syncthreads();
    if (tid == 0) {
        float t = bm[0];
        #pragma unroll
        for (int i = 1; i < 8; i++) t = fmaxf(t, bm[i]);
        s_m = t;
    }
    __syncthreads();
    m = s_m;
    float s = 0.f;
    for (int i = tid; i < S_; i += 256) s += __expf(row[i] - m);
    #pragma unroll
    for (int o = 16; o; o >>= 1) s += __shfl_xor_sync(0xffffffffu, s, o);
    if (lane == 0) bs[wrp] = s;
    __syncthreads();
    if (tid == 0) {
        float t = 0.f;
        #pragma unroll
        for (int i = 0; i < 8; i++) t += bs[i];
        s_inv = 1.0f / t;
    }
    __syncthreads();
    const float mm = s_m, inv = s_inv;
    const size_t ob = (size_t)z*S_*SP_ + (size_t)r*SP_;
    for (int c = tid; c < S_; c += 256)
        oh[ob + c] = __float2half(__expf(row[c] - mm) * inv);
}

// ======================= final V-softmax (smem row, 512 thr) =================
__global__ void softmax_big(float* __restrict__ data)
{
    extern __shared__ float row[];
    float* p = data + (size_t)blockIdx.x * V_;
    const int tid = threadIdx.x, lane = tid & 31, wrp = tid >> 5;
    __shared__ float bm[16], bs[16];
    __shared__ float s_m, s_inv;

    float m = -3.4e38f;
    for (int i = tid; i < V_; i += 512) { float v = p[i]; row[i] = v; m = fmaxf(m, v); }
    #pragma unroll
    for (int o = 16; o; o >>= 1) m = fmaxf(m, __shfl_xor_sync(0xffffffffu, m, o));
    if (lane == 0) bm[wrp] = m;
    __syncthreads();
    if (tid == 0) {
        float t = bm[0];
        #pragma unroll
        for (int i = 1; i < 16; i++) t = fmaxf(t, bm[i]);
        s_m = t;
    }
    __syncthreads();
    m = s_m;
    float s = 0.f;
    for (int i = tid; i < V_; i += 512) s += __expf(row[i] - m);
    #pragma unroll
    for (int o = 16; o; o >>= 1) s += __shfl_xor_sync(0xffffffffu, s, o);
    if (lane == 0) bs[wrp] = s;
    __syncthreads();
    if (tid == 0) {
        float t = 0.f;
        #pragma unroll
        for (int i = 0; i < 16; i++) t += bs[i];
        s_inv = 1.0f / t;
    }
    __syncthreads();
    const float mm = s_m, inv = s_inv;
    for (int i = tid; i < V_; i += 512)
        p[i] = __expf(row[i] - mm) * inv;
}

// ======================= residual add + LayerNorm ============================
__global__ void add_ln_kernel(const float* __restrict__ xin,
                              const float* __restrict__ res,
                              const float* __restrict__ g,
                              const float* __restrict__ b,
                              float* __restrict__ xout,
                              __half* __restrict__ oh)
{
    const int row = blockIdx.x, d = threadIdx.x;
    const int lane = d & 31, wrp = d >> 5;
    size_t idx = (size_t)row*D_ + d;
    float y = xin[idx] + res[idx];
    __shared__ float bsum[16], bsq[16];
    __shared__ float s_mu, s_rs;
    float s1 = y, s2 = y*y;
    #pragma unroll
    for (int o = 16; o; o >>= 1) {
        s1 += __shfl_xor_sync(0xffffffffu, s1, o);
        s2 += __shfl_xor_sync(0xffffffffu, s2, o);
    }
    if (lane == 0) { bsum[wrp] = s1; bsq[wrp] = s2; }
    __syncthreads();
    if (d == 0) {
        float a = 0.f, c = 0.f;
        #pragma unroll
        for (int i = 0; i < 16; i++) { a += bsum[i]; c += bsq[i]; }
        float mu = a * (1.0f/D_);
        float var = c * (1.0f/D_) - mu*mu;
        s_mu = mu; s_rs = rsqrtf(var + 1e-5f);
    }
    __syncthreads();
    float val = (y - s_mu) * s_rs * g[d] + b[d];
    xout[idx] = val;
    oh[idx] = __float2half(val);
}

// ======================= launcher ============================================
extern "C" void kernel_launch(void* const* d_in, const int* in_sizes, int n_in,
                              void* d_out, int out_size)
{
    (void)in_sizes; (void)n_in; (void)out_size;
    const int*   tokens = (const int*)  d_in[0];
    const float* emb  = (const float*)d_in[1];
    const float* wq   = (const float*)d_in[2];
    const float* bq   = (const float*)d_in[3];
    const float* wk   = (const float*)d_in[4];
    const float* bk   = (const float*)d_in[5];
    const float* wv   = (const float*)d_in[6];
    const float* bv   = (const float*)d_in[7];
    const float* wo   = (const float*)d_in[8];
    const float* bo   = (const float*)d_in[9];
    const float* ln1g = (const float*)d_in[10];
    const float* ln1b = (const float*)d_in[11];
    const float* w1   = (const float*)d_in[12];
    const float* b1   = (const float*)d_in[13];
    const float* w2   = (const float*)d_in[14];
    const float* b2   = (const float*)d_in[15];
    const float* ln2g = (const float*)d_in[16];
    const float* ln2b = (const float*)d_in[17];
    const float* fcw  = (const float*)d_in[18];
    const float* fcb  = (const float*)d_in[19];
    float* out = (float*)d_out;

    float *x,*t,*qkvb;
    __half *sc,*ah,*hh,*qh,*kh,*bh,*sh,*vh;
    cudaGetSymbolAddress((void**)&x,  g_x);  cudaGetSymbolAddress((void**)&t,  g_t);
    cudaGetSymbolAddress((void**)&sc, g_sc); cudaGetSymbolAddress((void**)&qkvb, g_qkvb);
    cudaGetSymbolAddress((void**)&ah, g_ah); cudaGetSymbolAddress((void**)&hh, g_hh);
    cudaGetSymbolAddress((void**)&qh, g_qh); cudaGetSymbolAddress((void**)&kh, g_kh);
    cudaGetSymbolAddress((void**)&bh, g_bh);
    cudaGetSymbolAddress((void**)&sh, g_sh); cudaGetSymbolAddress((void**)&vh, g_vh);

    cudaFuncSetAttribute(tmm_kernel, cudaFuncAttributeMaxDynamicSharedMemorySize, SMEM_TMM);
    cudaFuncSetAttribute(softmax_big, cudaFuncAttributeMaxDynamicSharedMemorySize, V_*4);

    embed_kernel<<<M_, D_>>>(tokens, emb, x, ah);

    const dim3 gQKV(1536/128, (M_+127)/128);
    const dim3 gDD (D_/128,  (M_+127)/128);
    const dim3 gFF (FF_/128, (M_+127)/128);
    const dim3 gSC ((S_+127)/128, (S_+127)/128, B_*H_);
    const dim3 gCX (1, (S_+127)/128, B_*H_);
    const dim3 tb (32, 8);

    for (int l = 0; l < L_; l++) {
        const float* lwq = wq + (size_t)l*D_*D_;
        const float* lwk = wk + (size_t)l*D_*D_;
        const float* lwv = wv + (size_t)l*D_*D_;
        const float* lwo = wo + (size_t)l*D_*D_;
        const float* lw1 = w1 + (size_t)l*D_*FF_;
        const float* lw2 = w2 + (size_t)l*FF_*D_;

        // ---- merged QKV projection ----
        qkv_bias<<<6, 256>>>(bq + l*D_, bk + l*D_, bv + l*D_, qkvb);
        wsplit_t<<<dim3(D_/32, D_/32), tb>>>(lwq, bh,           D_, D_);
        wsplit_t<<<dim3(D_/32, D_/32), tb>>>(lwk, bh +  512*D_, D_, D_);
        wsplit_t<<<dim3(D_/32, D_/32), tb>>>(lwv, bh + 1024*D_, D_, D_);
        tmm_kernel<<<gQKV, 256, SMEM_TMM>>>(ah, D_, bh, D_,
            qkvb, (float*)vh, qh, kh, D_, M_, 1536, D_, 0,0,0,0,0,0, 1.f, 0, 4);

        // ---- scores = QK^T/8 (K=64, single chunk) -> fp16 ----
        tmm_kernel<<<gSC, 256, SMEM_TMM>>>(qh, D_, kh, D_,
            nullptr, nullptr, sc, nullptr, S_, S_, S_, 64,
            (long long)S_*D_, HD_, (long long)S_*D_, HD_,
            (long long)H_*S_*S_, (long long)S_*S_, 0.125f, 0, 2);

        softmax_split<<<B_*H_*S_, 256>>>(sc, sh);

        // ---- ctx = probs @ V^T (K=1024 padded) -> fp16 into qh ----
        tmm_kernel<<<gCX, 256, SMEM_TMM>>>(sh, SP_, vh, SP_,
            nullptr, nullptr, qh, nullptr, D_, S_, HD_, SP_,
            (long long)H_*S_*SP_, (long long)S_*SP_,
            (long long)H_*HD_*SP_, (long long)HD_*SP_,
            (long long)S_*D_, HD_, 1.f, 0, 2);

        // ---- output projection ----
        wsplit_t<<<dim3(D_/32, D_/32), tb>>>(lwo, bh, D_, D_);
        tmm_kernel<<<gDD, 256, SMEM_TMM>>>(qh, D_, bh, D_,
            bo + l*D_, t, nullptr, nullptr, D_, M_, D_, D_, 0,0,0,0,0,0, 1.f, 0, 0);

        add_ln_kernel<<<M_, D_>>>(x, t, ln1g + l*D_, ln1b + l*D_, x, ah);

        // ---- FFN ----
        wsplit_t<<<dim3(FF_/32, D_/32), tb>>>(lw1, bh, D_, FF_);
        tmm_kernel<<<gFF, 256, SMEM_TMM>>>(ah, D_, bh, D_,
            b1 + l*FF_, nullptr, hh, nullptr, FF_, M_, FF_, D_, 0,0,0,0,0,0, 1.f, 1, 2);
        wsplit_t<<<dim3(D_/32, FF_/32), tb>>>(lw2, bh, FF_, D_);
        tmm_kernel<<<gDD, 256, SMEM_TMM>>>(hh, FF_, bh, FF_,
            b2 + l*D_, t, nullptr, nullptr, D_, M_, D_, FF_, 0,0,0,0,0,0, 1.f, 0, 0);

        add_ln_kernel<<<M_, D_>>>(x, t, ln2g + l*D_, ln2b + l*D_, x, ah);
    }

    // ---- logits + softmax ----
    wsplit_t<<<dim3(V_/32, D_/32), tb>>>(fcw, bh, D_, V_);
    tmm_kernel<<<dim3(V_/128, (M_+127)/128), 256, SMEM_TMM>>>(ah, D_, bh, D_,
        fcb, out, nullptr, nullptr, V_, M_, V_, D_, 0,0,0,0,0,0, 1.f, 0, 0);
    softmax_big<<<M_, 512, V_*4>>>(out);
}